// round 16
// baseline (speedup 1.0000x reference)
#include <cuda_runtime.h>
#include <cuda_fp16.h>
#include <math.h>
#include <stdint.h>

#define BATCH   4
#define LSEQ    2048
#define ROWS    (BATCH*LSEQ)      // 8192
#define DMODEL  768
#define DINNER  1536
#define NHEADS  24
#define HEADDIM 64
#define DSTATE  128
#define CONVDIM 1792
#define DPROJ   3352

#define NSEG    32
#define SEGLEN  (LSEQ/NSEG)       // 64
#define STATESZ (HEADDIM*DSTATE)  // 8192
#define STATEPAIRS (STATESZ/2)    // 4096

// -------- scratch (device globals; no allocation allowed) --------
__device__ float g_zxbcdt[(size_t)ROWS * DPROJ];
__device__ float g_xBC[(size_t)ROWS * CONVDIM];
__device__ float g_dt[ROWS * NHEADS];
__device__ float g_y[(size_t)ROWS * DINNER];
__device__ float g_states[(size_t)BATCH*NHEADS*NSEG*STATESZ];
// pre-split bf16 hi/lo of xBC's B|C columns: [row][128 pairs]
__device__ uint32_t g_bcH[(size_t)ROWS*128];
__device__ uint32_t g_bcL[(size_t)ROWS*128];
// pre-split bf16 hi/lo segment start states
__device__ uint32_t g_hsH[(size_t)BATCH*NHEADS*NSEG*STATEPAIRS];
__device__ uint32_t g_hsL[(size_t)BATCH*NHEADS*NSEG*STATEPAIRS];
// fp16 packed-pair operands for projection GEMMs
__device__ uint32_t g_feat16[(size_t)ROWS*DMODEL/2];
__device__ uint32_t g_ipw16[(size_t)DPROJ*DMODEL/2];
__device__ uint32_t g_opw16[(size_t)DMODEL*DINNER/2];
__device__ uint32_t g_y16[(size_t)ROWS*DINNER/2];

// =================================================================
// helpers
// =================================================================
__device__ __forceinline__ uint32_t packbf2(float f0, float f1) {
    uint32_t r;
    asm("cvt.rn.bf16x2.f32 %0, %1, %2;" : "=r"(r) : "f"(f1), "f"(f0));
    return r;
}
__device__ __forceinline__ void bsplit2(float f0, float f1, uint32_t& H, uint32_t& L) {
    H = packbf2(f0, f1);
    float h0 = __uint_as_float(H << 16);
    float h1 = __uint_as_float(H & 0xffff0000u);
    L = packbf2(f0 - h0, f1 - h1);
}
__device__ __forceinline__ uint32_t packh2(float f0, float f1) {
    __half2 h = __float22half2_rn(make_float2(f0, f1));
    return *(uint32_t*)&h;
}
__device__ __forceinline__ float ubf(uint32_t w, int hi) {
    return __uint_as_float(hi ? (w & 0xffff0000u) : (w << 16));
}

#define CPA16(dst, src) \
    asm volatile("cp.async.cg.shared.global [%0], [%1], 16;\n" \
                 :: "r"(dst), "l"(src))
#define CPA16P(dst, src, valid) \
    asm volatile("cp.async.cg.shared.global [%0], [%1], 16, %2;\n" \
                 :: "r"(dst), "l"(src), "r"((valid) ? 16 : 0))
#define CPA_COMMIT() asm volatile("cp.async.commit_group;\n" ::: "memory")
#define CPA_WAIT0()  asm volatile("cp.async.wait_group 0;\n" ::: "memory")
#define CPA_WAIT1()  asm volatile("cp.async.wait_group 1;\n" ::: "memory")

#define MMA_BF16(d, a, b) \
    asm volatile("mma.sync.aligned.m16n8k16.row.col.f32.bf16.bf16.f32 " \
                 "{%0,%1,%2,%3},{%4,%5,%6,%7},{%8,%9},{%0,%1,%2,%3};\n" \
                 : "+f"((d)[0]), "+f"((d)[1]), "+f"((d)[2]), "+f"((d)[3]) \
                 : "r"((a)[0]), "r"((a)[1]), "r"((a)[2]), "r"((a)[3]), \
                   "r"((b)[0]), "r"((b)[1]))
#define MMA_F16(d, a, b) \
    asm volatile("mma.sync.aligned.m16n8k16.row.col.f32.f16.f16.f32 " \
                 "{%0,%1,%2,%3},{%4,%5,%6,%7},{%8,%9},{%0,%1,%2,%3};\n" \
                 : "+f"((d)[0]), "+f"((d)[1]), "+f"((d)[2]), "+f"((d)[3]) \
                 : "r"((a)[0]), "r"((a)[1]), "r"((a)[2]), "r"((a)[3]), \
                   "r"((b)[0]), "r"((b)[1]))
#define MMA3B(d, aH, aL, bH, bL) do { \
    MMA_BF16(d, aL, bH); \
    MMA_BF16(d, aH, bL); \
    MMA_BF16(d, aH, bH); } while (0)

#define LDSM_X4(r0, r1, r2, r3, a) \
    asm volatile("ldmatrix.sync.aligned.m8n8.x4.shared.b16 {%0,%1,%2,%3}, [%4];" \
                 : "=r"(r0), "=r"(r1), "=r"(r2), "=r"(r3) : "r"(a))

#define TSTRIDE 68   // words per 64-pair tile row (C/B initial, inter tiles)
#define XSTRIDE 36   // words per 32-pair tile row (X, M~ k, wB)

// =================================================================
// fp32 -> packed fp16 pair conversion
// =================================================================
__global__ __launch_bounds__(256) void tofp16_kernel(
    const float* __restrict__ src, uint32_t* __restrict__ dst)
{
    const int idx = blockIdx.x * 256 + threadIdx.x;
    float2 v = ((const float2*)src)[idx];
    dst[idx] = packh2(v.x, v.y);
}

// =================================================================
// fp16 tensor-core GEMM (NT): BM=128, 3-stage cp.async (R14 passing)
// =================================================================
#define GP_STAGE 5120
#define GP_SMEM  (3 * GP_STAGE * 4)

__global__ __launch_bounds__(256) void gemm_fp16(
    const uint32_t* __restrict__ A16, const uint32_t* __restrict__ B16,
    float* __restrict__ C, int M, int N, int Kp,
    const float* __restrict__ gate)
{
    extern __shared__ uint32_t gsm[];

    const int tid  = threadIdx.x;
    const int lane = tid & 31;
    const int warp = tid >> 5;
    const int wm   = warp >> 2;
    const int wn   = warp & 3;
    const int m0   = blockIdx.y * 128;
    const int n0   = blockIdx.x * 128;
    const int qr   = lane >> 2;
    const int ql   = lane & 3;

    const uint32_t* csrc[4];
    int coff[4];
    bool cval[4];
    #pragma unroll
    for (int q = 0; q < 4; q++) {
        int e = tid + q * 256;
        bool isB = e >= 512;
        int r = (e & 511) >> 2;
        int g = (e & 3) * 4;
        coff[q] = (isB ? 2560 : 0) + r * 20 + g;
        int grow = isB ? min(n0 + r, N - 1) : (m0 + r);
        cval[q] = isB ? ((n0 + r) < N) : true;
        csrc[q] = (isB ? B16 : A16) + (size_t)grow * Kp + g;
    }

    const int a_row = wm * 64 + (lane & 15);
    const int a_kp  = (lane >> 4) << 2;
    const int b_row = wn * 32 + ((lane >> 4) << 3) + (lane & 7);
    const int b_kp  = ((lane >> 3) & 1) << 2;

    float acc[4][4][4];
    #pragma unroll
    for (int i = 0; i < 4; i++)
        #pragma unroll
        for (int j = 0; j < 4; j++)
            #pragma unroll
            for (int r = 0; r < 4; r++) acc[i][j][r] = 0.f;

    const int KT = Kp / 16;

    #define GF_FILL(kt, s)                                                       \
    {                                                                            \
        const size_t ko = (size_t)(kt) * 16;                                     \
        uint32_t* stg = gsm + (s) * GP_STAGE;                                    \
        _Pragma("unroll")                                                        \
        for (int q = 0; q < 4; q++) {                                            \
            uint32_t d = (uint32_t)__cvta_generic_to_shared(&stg[coff[q]]);      \
            CPA16P(d, csrc[q] + ko, cval[q]);                                    \
        }                                                                        \
        CPA_COMMIT();                                                            \
    }

    GF_FILL(0, 0);
    if (KT > 1) GF_FILL(1, 1);

    int st = 0;
    for (int kt = 0; kt < KT; kt++) {
        if (kt + 1 < KT) { CPA_WAIT1(); } else { CPA_WAIT0(); }
        __syncthreads();

        if (kt + 2 < KT) {
            int ns = st + 2; if (ns >= 3) ns -= 3;
            GF_FILL(kt + 2, ns);
        }

        const uint32_t* As_ = gsm + st * GP_STAGE;
        const uint32_t* Bs_ = As_ + 2560;

        #pragma unroll
        for (int kb = 0; kb < 2; kb++) {
            const int kp0 = kb * 8;
            uint32_t a[4][4], b[4][2];
            #pragma unroll
            for (int mf = 0; mf < 4; mf++) {
                uint32_t ad = (uint32_t)__cvta_generic_to_shared(
                    &As_[(a_row + mf * 16) * 20 + kp0 + a_kp]);
                LDSM_X4(a[mf][0], a[mf][1], a[mf][2], a[mf][3], ad);
            }
            #pragma unroll
            for (int nf2 = 0; nf2 < 2; nf2++) {
                uint32_t bd = (uint32_t)__cvta_generic_to_shared(
                    &Bs_[(b_row + nf2 * 16) * 20 + kp0 + b_kp]);
                LDSM_X4(b[2*nf2][0], b[2*nf2][1], b[2*nf2+1][0], b[2*nf2+1][1], bd);
            }
            #pragma unroll
            for (int mf = 0; mf < 4; mf++)
                #pragma unroll
                for (int nf = 0; nf < 4; nf++)
                    MMA_F16(acc[mf][nf], a[mf], b[nf]);
        }

        st++; if (st >= 3) st = 0;
    }
    #undef GF_FILL

    float scale = 1.f;
    if (gate) { float g = *gate; scale = 1.f / (1.f + expf(-g)); }

    #pragma unroll
    for (int mf = 0; mf < 4; mf++) {
        const int r = m0 + wm * 64 + mf * 16 + qr;
        #pragma unroll
        for (int nf = 0; nf < 4; nf++) {
            const int c = n0 + wn * 32 + nf * 8 + ql * 2;
            if (c < N) {
                float2 v0 = make_float2(acc[mf][nf][0] * scale, acc[mf][nf][1] * scale);
                float2 v1 = make_float2(acc[mf][nf][2] * scale, acc[mf][nf][3] * scale);
                *(float2*)&C[(size_t)r * N + c]       = v0;
                *(float2*)&C[(size_t)(r + 8) * N + c] = v1;
            }
        }
    }
}

// =================================================================
// fp16 GEMM variant: BM=64, BN=128 — for out_proj (better wave fit,
// 46KB smem -> 3 CTAs/SM). Warp tile 32x32, acc 32 regs.
// stage layout: A [64][20] @0, B [128][20] @1280; stage = 3840 words
// =================================================================
#define GQ_STAGE 3840
#define GQ_SMEM  (3 * GQ_STAGE * 4)   // 46080 bytes

__global__ __launch_bounds__(256) void gemm_fp16_bm64(
    const uint32_t* __restrict__ A16, const uint32_t* __restrict__ B16,
    float* __restrict__ C, int M, int N, int Kp,
    const float* __restrict__ gate)
{
    extern __shared__ uint32_t gsm[];

    const int tid  = threadIdx.x;
    const int lane = tid & 31;
    const int warp = tid >> 5;
    const int wm   = warp >> 2;      // 0..1
    const int wn   = warp & 3;       // 0..3
    const int m0   = blockIdx.y * 64;
    const int n0   = blockIdx.x * 128;
    const int qr   = lane >> 2;
    const int ql   = lane & 3;

    // fill mapping: 768 chunks (A 256 + B 512); 3 per thread
    const uint32_t* csrc[3];
    int coff[3];
    bool cval[3];
    #pragma unroll
    for (int q = 0; q < 3; q++) {
        int e = tid + q * 256;
        bool isB = e >= 256;
        int eb = isB ? (e - 256) : e;
        int r = eb >> 2;
        int g = (eb & 3) * 4;
        coff[q] = (isB ? 1280 : 0) + r * 20 + g;
        int grow = isB ? min(n0 + r, N - 1) : (m0 + r);
        cval[q] = isB ? ((n0 + r) < N) : true;
        csrc[q] = (isB ? B16 : A16) + (size_t)grow * Kp + g;
    }

    const int a_row = wm * 32 + (lane & 15);
    const int a_kp  = (lane >> 4) << 2;
    const int b_row = wn * 32 + ((lane >> 4) << 3) + (lane & 7);
    const int b_kp  = ((lane >> 3) & 1) << 2;

    float acc[2][4][4];
    #pragma unroll
    for (int i = 0; i < 2; i++)
        #pragma unroll
        for (int j = 0; j < 4; j++)
            #pragma unroll
            for (int r = 0; r < 4; r++) acc[i][j][r] = 0.f;

    const int KT = Kp / 16;

    #define GQ_FILL(kt, s)                                                       \
    {                                                                            \
        const size_t ko = (size_t)(kt) * 16;                                     \
        uint32_t* stg = gsm + (s) * GQ_STAGE;                                    \
        _Pragma("unroll")                                                        \
        for (int q = 0; q < 3; q++) {                                            \
            uint32_t d = (uint32_t)__cvta_generic_to_shared(&stg[coff[q]]);      \
            CPA16P(d, csrc[q] + ko, cval[q]);                                    \
        }                                                                        \
        CPA_COMMIT();                                                            \
    }

    GQ_FILL(0, 0);
    if (KT > 1) GQ_FILL(1, 1);

    int st = 0;
    for (int kt = 0; kt < KT; kt++) {
        if (kt + 1 < KT) { CPA_WAIT1(); } else { CPA_WAIT0(); }
        __syncthreads();

        if (kt + 2 < KT) {
            int ns = st + 2; if (ns >= 3) ns -= 3;
            GQ_FILL(kt + 2, ns);
        }

        const uint32_t* As_ = gsm + st * GQ_STAGE;
        const uint32_t* Bs_ = As_ + 1280;

        #pragma unroll
        for (int kb = 0; kb < 2; kb++) {
            const int kp0 = kb * 8;
            uint32_t a[2][4], b[4][2];
            #pragma unroll
            for (int mf = 0; mf < 2; mf++) {
                uint32_t ad = (uint32_t)__cvta_generic_to_shared(
                    &As_[(a_row + mf * 16) * 20 + kp0 + a_kp]);
                LDSM_X4(a[mf][0], a[mf][1], a[mf][2], a[mf][3], ad);
            }
            #pragma unroll
            for (int nf2 = 0; nf2 < 2; nf2++) {
                uint32_t bd = (uint32_t)__cvta_generic_to_shared(
                    &Bs_[(b_row + nf2 * 16) * 20 + kp0 + b_kp]);
                LDSM_X4(b[2*nf2][0], b[2*nf2][1], b[2*nf2+1][0], b[2*nf2+1][1], bd);
            }
            #pragma unroll
            for (int mf = 0; mf < 2; mf++)
                #pragma unroll
                for (int nf = 0; nf < 4; nf++)
                    MMA_F16(acc[mf][nf], a[mf], b[nf]);
        }

        st++; if (st >= 3) st = 0;
    }
    #undef GQ_FILL

    float scale = 1.f;
    if (gate) { float g = *gate; scale = 1.f / (1.f + expf(-g)); }

    #pragma unroll
    for (int mf = 0; mf < 2; mf++) {
        const int r = m0 + wm * 32 + mf * 16 + qr;
        #pragma unroll
        for (int nf = 0; nf < 4; nf++) {
            const int c = n0 + wn * 32 + nf * 8 + ql * 2;
            if (c < N) {
                float2 v0 = make_float2(acc[mf][nf][0] * scale, acc[mf][nf][1] * scale);
                float2 v1 = make_float2(acc[mf][nf][2] * scale, acc[mf][nf][3] * scale);
                *(float2*)&C[(size_t)r * N + c]       = v0;
                *(float2*)&C[(size_t)(r + 8) * N + c] = v1;
            }
        }
    }
}

// =================================================================
// conv_silu (pairwise) + fused bf16 hi/lo split of B|C channels (R14)
// =================================================================
__global__ __launch_bounds__(256) void conv_silu_kernel(
    const float* __restrict__ conv_w, const float* __restrict__ conv_b)
{
    const long idx = (long)blockIdx.x * 256 + threadIdx.x;
    const int  cp  = (int)(idx % (CONVDIM/2));
    const long row = idx / (CONVDIM/2);
    const int  l   = (int)(row % LSEQ);
    const int  c   = cp * 2;

    float2 acc = make_float2(conv_b[c], conv_b[c+1]);
    float4 wa = *(const float4*)&conv_w[c*4];
    float4 wb = *(const float4*)&conv_w[(c+1)*4];
    const float* base = g_zxbcdt + (size_t)row * DPROJ + DINNER + c;
    if (l >= 3) { float2 v = *(const float2*)(base - 3*DPROJ);
                  acc.x = fmaf(v.x, wa.x, acc.x); acc.y = fmaf(v.y, wb.x, acc.y); }
    if (l >= 2) { float2 v = *(const float2*)(base - 2*DPROJ);
                  acc.x = fmaf(v.x, wa.y, acc.x); acc.y = fmaf(v.y, wb.y, acc.y); }
    if (l >= 1) { float2 v = *(const float2*)(base - 1*DPROJ);
                  acc.x = fmaf(v.x, wa.z, acc.x); acc.y = fmaf(v.y, wb.z, acc.y); }
    { float2 v = *(const float2*)base;
      acc.x = fmaf(v.x, wa.w, acc.x); acc.y = fmaf(v.y, wb.w, acc.y); }

    acc.x = acc.x / (1.f + expf(-acc.x));
    acc.y = acc.y / (1.f + expf(-acc.y));
    *(float2*)&g_xBC[row * CONVDIM + c] = acc;

    if (c >= DINNER) {
        const int np = (c - DINNER) >> 1;
        uint32_t hh, ll;
        bsplit2(acc.x, acc.y, hh, ll);
        g_bcH[row * 128 + np] = hh;
        g_bcL[row * 128 + np] = ll;
    }
}

// =================================================================
// dt = softplus(dt_raw + dt_bias)
// =================================================================
__global__ __launch_bounds__(256) void dt_kernel(const float* __restrict__ dt_bias)
{
    const int idx = blockIdx.x * 256 + threadIdx.x;
    const int h   = idx % NHEADS;
    const int row = idx / NHEADS;
    float v  = g_zxbcdt[(size_t)row * DPROJ + (DINNER + CONVDIM) + h] + dt_bias[h];
    float sp = (v > 20.f) ? v : log1pf(expf(v));
    g_dt[idx] = sp;
}

// =================================================================
// K1: fused per-chunk kernel — T=64, 256 threads (R15 passing)
// =================================================================
#define K1_SMEM_U32 22724
#define K3_SMEM_U32 17476

__global__ __launch_bounds__(256) void chunk_fused_kernel(
    const float* __restrict__ A_log, const float* __restrict__ Dvec)
{
    extern __shared__ uint32_t smu[];
    uint32_t* CHs = smu;
    uint32_t* CLs = smu + 4352;
    uint32_t* BHs = smu + 8704;
    uint32_t* BLs = smu + 13312;
    uint32_t* XHs = smu + 17920;
    uint32_t* XLs = smu + 20224;
    float*    sa  = (float*)(smu + 22528);
    float*    sdt = (float*)(smu + 22592);
    float*    sw  = (float*)(smu + 22656);
    float*    wsum2 = (float*)(smu + 22720);

    const int blk = blockIdx.x;
    const int bh = blk >> 5, seg = blk & (NSEG - 1);
    const int b = bh / NHEADS, h = bh % NHEADS;
    const int tid = threadIdx.x, lane = tid & 31, warp = tid >> 5;
    const int qr = lane >> 2, ql = lane & 3;
    const size_t rowbase = (size_t)b * LSEQ + seg * SEGLEN;

    const int lrow = lane & 15;
    const int lkp  = (lane >> 4) << 2;
    const int brow = ((lane >> 4) << 3) + (lane & 7);
    const int bkp  = ((lane >> 3) & 1) << 2;

    #pragma unroll
    for (int i = 0; i < 4; i++) {
        int e = tid + i * 256;
        int t = e >> 4, g = (e & 15) * 4;
        const size_t srcw = (rowbase + t) * 128 + g;
        CPA16((uint32_t)__cvta_generic_to_shared(&BHs[t*TSTRIDE + g]), g_bcH + srcw);
        CPA16((uint32_t)__cvta_generic_to_shared(&BLs[t*TSTRIDE + g]), g_bcL + srcw);
        CPA16((uint32_t)__cvta_generic_to_shared(&CHs[t*TSTRIDE + g]), g_bcH + srcw + 64);
        CPA16((uint32_t)__cvta_generic_to_shared(&CLs[t*TSTRIDE + g]), g_bcL + srcw + 64);
    }
    CPA_COMMIT();

    #pragma unroll
    for (int i = 0; i < 8; i++) {
        int e = tid + i * 256;
        int p = e & 63, sp = e >> 6;
        const float* s0 = g_xBC + (rowbase + 2*sp) * CONVDIM + h * HEADDIM + p;
        uint32_t hh, ll;
        bsplit2(s0[0], s0[CONVDIM], hh, ll);
        XHs[p*XSTRIDE + sp] = hh; XLs[p*XSTRIDE + sp] = ll;
    }

    const float Aneg = -expf(A_log[h]);
    float vdt = 0.f, acs = 0.f;
    if (tid < SEGLEN) {
        vdt = g_dt[(rowbase + tid) * NHEADS + h];
        acs = vdt;
        #pragma unroll
        for (int o = 1; o < 32; o <<= 1) {
            float nv = __shfl_up_sync(0xffffffffu, acs, o);
            if (lane >= o) acs += nv;
        }
        if (lane == 31) wsum2[warp] = acs;
    }
    __syncthreads();
    if (tid < SEGLEN) {
        float tot = wsum2[0] + wsum2[1];
        float pre = (warp == 1) ? wsum2[0] : 0.f;
        float a = acs + pre;
        sa[tid]  = a;
        sdt[tid] = vdt;
        sw[tid]  = vdt * __expf(Aneg * (tot - a));
    }
    CPA_WAIT0();
    __syncthreads();

    // GEMM1: M = C @ B^T (64x64, K=128), skip masked warp tiles
    float mreg[4][4];
    #pragma unroll
    for (int j = 0; j < 4; j++)
        #pragma unroll
        for (int r = 0; r < 4; r++) mreg[j][r] = 0.f;

    const int m1 = (warp >> 1) * 16, n1 = (warp & 1) * 32;
    if (n1 < m1 + 16) {
        #pragma unroll
        for (int kb = 0; kb < 8; kb++) {
            const int kp0 = kb * 8;
            uint32_t aH[4], aL[4], bH[4][2], bL[4][2];
            {
                const int r = (m1 + lrow) * TSTRIDE + kp0 + lkp;
                uint32_t ad = (uint32_t)__cvta_generic_to_shared(&CHs[r]);
                LDSM_X4(aH[0], aH[1], aH[2], aH[3], ad);
                ad = (uint32_t)__cvta_generic_to_shared(&CLs[r]);
                LDSM_X4(aL[0], aL[1], aL[2], aL[3], ad);
            }
            #pragma unroll
            for (int nf2 = 0; nf2 < 2; nf2++) {
                const int r = (n1 + brow + nf2*16) * TSTRIDE + kp0 + bkp;
                uint32_t bd = (uint32_t)__cvta_generic_to_shared(&BHs[r]);
                LDSM_X4(bH[2*nf2][0], bH[2*nf2][1], bH[2*nf2+1][0], bH[2*nf2+1][1], bd);
                bd = (uint32_t)__cvta_generic_to_shared(&BLs[r]);
                LDSM_X4(bL[2*nf2][0], bL[2*nf2][1], bL[2*nf2+1][0], bL[2*nf2+1][1], bd);
            }
            #pragma unroll
            for (int nf = 0; nf < 4; nf++)
                MMA3B(mreg[nf], aH, aL, bH[nf], bL[nf]);
        }
    }
    __syncthreads();

    {
        int tA = m1 + qr, tB = tA + 8;
        float aA = sa[tA], aB = sa[tB];
        #pragma unroll
        for (int nf = 0; nf < 4; nf++) {
            int sp = (n1 >> 1) + nf*4 + ql;
            int s0 = 2*sp, s1 = s0 + 1;
            float as0 = sa[s0], as1 = sa[s1];
            float d0 = sdt[s0], d1 = sdt[s1];
            float v00 = (s0 <= tA) ? mreg[nf][0] * __expf(Aneg*(aA-as0)) * d0 : 0.f;
            float v01 = (s1 <= tA) ? mreg[nf][1] * __expf(Aneg*(aA-as1)) * d1 : 0.f;
            float v10 = (s0 <= tB) ? mreg[nf][2] * __expf(Aneg*(aB-as0)) * d0 : 0.f;
            float v11 = (s1 <= tB) ? mreg[nf][3] * __expf(Aneg*(aB-as1)) * d1 : 0.f;
            uint32_t hh, ll;
            bsplit2(v00, v01, hh, ll); CHs[tA*TSTRIDE + sp] = hh; CLs[tA*TSTRIDE + sp] = ll;
            bsplit2(v10, v11, hh, ll); CHs[tB*TSTRIDE + sp] = hh; CLs[tB*TSTRIDE + sp] = ll;
        }
    }

    #pragma unroll
    for (int i = 0; i < 16; i++) {
        int e = tid + i * 256;
        int n = e & 127, sp = e >> 7;
        const float* s0 = g_xBC + (rowbase + 2*sp) * CONVDIM + DINNER + n;
        float f0 = s0[0] * sw[2*sp];
        float f1 = s0[CONVDIM] * sw[2*sp + 1];
        uint32_t hh, ll;
        bsplit2(f0, f1, hh, ll);
        BHs[n*XSTRIDE + sp] = hh; BLs[n*XSTRIDE + sp] = ll;
    }
    __syncthreads();

    // GEMM2: Y = M~ @ X (64t x 64p, K=64)
    {
        float yreg[4][4];
        #pragma unroll
        for (int j = 0; j < 4; j++)
            #pragma unroll
            for (int r = 0; r < 4; r++) yreg[j][r] = 0.f;

        const int m2 = (warp >> 1) * 16, n2 = (warp & 1) * 32;
        #pragma unroll
        for (int kb = 0; kb < 4; kb++) {
            const int kp0 = kb * 8;
            uint32_t aH[4], aL[4], bH[4][2], bL[4][2];
            {
                const int r = (m2 + lrow) * TSTRIDE + kp0 + lkp;
                uint32_t ad = (uint32_t)__cvta_generic_to_shared(&CHs[r]);
                LDSM_X4(aH[0], aH[1], aH[2], aH[3], ad);
                ad = (uint32_t)__cvta_generic_to_shared(&CLs[r]);
                LDSM_X4(aL[0], aL[1], aL[2], aL[3], ad);
            }
            #pragma unroll
            for (int nf2 = 0; nf2 < 2; nf2++) {
                const int r = (n2 + brow + nf2*16) * XSTRIDE + kp0 + bkp;
                uint32_t bd = (uint32_t)__cvta_generic_to_shared(&XHs[r]);
                LDSM_X4(bH[2*nf2][0], bH[2*nf2][1], bH[2*nf2+1][0], bH[2*nf2+1][1], bd);
                bd = (uint32_t)__cvta_generic_to_shared(&XLs[r]);
                LDSM_X4(bL[2*nf2][0], bL[2*nf2][1], bL[2*nf2+1][0], bL[2*nf2+1][1], bd);
            }
            #pragma unroll
            for (int nf = 0; nf < 4; nf++)
                MMA3B(yreg[nf], aH, aL, bH[nf], bL[nf]);
        }

        const float Dh = Dvec[h];
        {
            int t = m2 + qr;
            const int sp0 = t >> 1, hi0 = t & 1;
            const int sp1 = (t + 8) >> 1, hi1 = t & 1;
            #pragma unroll
            for (int nf = 0; nf < 4; nf++) {
                int p0 = n2 + nf*8 + ql*2;
                float x00 = ubf(XHs[p0*XSTRIDE + sp0], hi0) + ubf(XLs[p0*XSTRIDE + sp0], hi0);
                float x01 = ubf(XHs[(p0+1)*XSTRIDE + sp0], hi0) + ubf(XLs[(p0+1)*XSTRIDE + sp0], hi0);
                float x10 = ubf(XHs[p0*XSTRIDE + sp1], hi1) + ubf(XLs[p0*XSTRIDE + sp1], hi1);
                float x11 = ubf(XHs[(p0+1)*XSTRIDE + sp1], hi1) + ubf(XLs[(p0+1)*XSTRIDE + sp1], hi1);
                float2 o;
                o.x = yreg[nf][0] + Dh * x00;
                o.y = yreg[nf][1] + Dh * x01;
                *(float2*)&g_y[(rowbase + t)*DINNER + h*HEADDIM + p0] = o;
                o.x = yreg[nf][2] + Dh * x10;
                o.y = yreg[nf][3] + Dh * x11;
                *(float2*)&g_y[(rowbase + t + 8)*DINNER + h*HEADDIM + p0] = o;
            }
        }
    }

    // GEMM3: S = X^T @ (w*B) (64p x 128n, K=64)
    {
        float sreg[2][4][4];
        #pragma unroll
        for (int i = 0; i < 2; i++)
            #pragma unroll
            for (int j = 0; j < 4; j++)
                #pragma unroll
                for (int r = 0; r < 4; r++) sreg[i][j][r] = 0.f;

        const int m3 = (warp >> 2) * 32, n3 = (warp & 3) * 32;
        #pragma unroll
        for (int kb = 0; kb < 4; kb++) {
            const int kp0 = kb * 8;
            uint32_t aH[2][4], aL[2][4], bH[4][2], bL[4][2];
            #pragma unroll
            for (int mf = 0; mf < 2; mf++) {
                const int r = (m3 + lrow + mf*16) * XSTRIDE + kp0 + lkp;
                uint32_t ad = (uint32_t)__cvta_generic_to_shared(&XHs[r]);
                LDSM_X4(aH[mf][0], aH[mf][1], aH[mf][2], aH[mf][3], ad);
                ad = (uint32_t)__cvta_generic_to_shared(&XLs[r]);
                LDSM_X4(aL[mf][0], aL[mf][1], aL[mf][2], aL[mf][3], ad);
            }
            #pragma unroll
            for (int nf2 = 0; nf2 < 2; nf2++) {
                const int r = (n3 + brow + nf2*16) * XSTRIDE + kp0 + bkp;
                uint32_t bd = (uint32_t)__cvta_generic_to_shared(&BHs[r]);
                LDSM_X4(bH[2*nf2][0], bH[2*nf2][1], bH[2*nf2+1][0], bH[2*nf2+1][1], bd);
                bd = (uint32_t)__cvta_generic_to_shared(&BLs[r]);
                LDSM_X4(bL[2*nf2][0], bL[2*nf2][1], bL[2*nf2+1][0], bL[2*nf2+1][1], bd);
            }
            #pragma unroll
            for (int mf = 0; mf < 2; mf++)
                #pragma unroll
                for (int nf = 0; nf < 4; nf++)
                    MMA3B(sreg[mf][nf], aH[mf], aL[mf], bH[nf], bL[nf]);
        }

        const size_t sbase = ((size_t)bh * NSEG + seg) * STATESZ;
        #pragma unroll
        for (int mf = 0; mf < 2; mf++) {
            int p = m3 + mf*16 + qr;
            #pragma unroll
            for (int nf = 0; nf < 4; nf++) {
                int n0 = n3 + nf*8 + ql*2;
                float2 o0 = make_float2(sreg[mf][nf][0], sreg[mf][nf][1]);
                float2 o1 = make_float2(sreg[mf][nf][2], sreg[mf][nf][3]);
                *(float2*)&g_states[sbase + (size_t)p * DSTATE + n0]       = o0;
                *(float2*)&g_states[sbase + (size_t)(p + 8) * DSTATE + n0] = o1;
            }
        }
    }
}

// =================================================================
// K2: combine — NSEG=32, emits pre-split bf16 hi/lo hstart pairs
// =================================================================
__global__ __launch_bounds__(256) void combine_kernel(const float* __restrict__ A_log)
{
    const int bh = blockIdx.x;
    const int b = bh / NHEADS, h = bh % NHEADS;
    const int tid = threadIdx.x;

    __shared__ float part[256];
    __shared__ float Esh[NSEG];

    {
        const int k = tid >> 3, i = tid & 7;
        float s = 0.f;
        const size_t base = ((size_t)b*LSEQ + k*SEGLEN + i*8)*NHEADS + h;
        #pragma unroll
        for (int t = 0; t < 8; t++) s += g_dt[base + (size_t)t*NHEADS];
        part[tid] = s;
    }
    __syncthreads();
    if (tid < NSEG) {
        float s = 0.f;
        #pragma unroll
        for (int i = 0; i < 8; i++) s += part[tid*8 + i];
        Esh[tid] = expf(-expf(A_log[h]) * s);
    }
    __syncthreads();

    float2 hs[16];
    #pragma unroll
    for (int k2 = 0; k2 < 16; k2++) hs[k2] = make_float2(0.f, 0.f);

    for (int seg = 0; seg < NSEG; seg++) {
        const size_t pbase = ((size_t)bh*NSEG + seg)*STATEPAIRS;
        const float E = Esh[seg];
        #pragma unroll
        for (int k2 = 0; k2 < 16; k2++) {
            const size_t j = pbase + k2*256 + tid;
            uint32_t hh, ll;
            bsplit2(hs[k2].x, hs[k2].y, hh, ll);
            g_hsH[j] = hh;  g_hsL[j] = ll;
            float2 s = ((const float2*)g_states)[j];
            hs[k2].x = fmaf(hs[k2].x, E, s.x);
            hs[k2].y = fmaf(hs[k2].y, E, s.y);
        }
    }
}

// =================================================================
// K3: inter-chunk — T=64, 256 threads (R15 passing)
// =================================================================
__global__ __launch_bounds__(256) void inter_kernel(const float* __restrict__ A_log)
{
    extern __shared__ uint32_t smu[];
    uint32_t* CH2 = smu;
    uint32_t* CL2 = smu + 4352;
    uint32_t* HHs = smu + 8704;
    uint32_t* HLs = smu + 13056;
    float*    su  = (float*)(smu + 17408);
    float*    wsum2 = (float*)(smu + 17472);

    const int blk = blockIdx.x;
    const int bh = blk >> 5, seg = blk & (NSEG - 1);
    const int b = bh / NHEADS, h = bh % NHEADS;
    const int tid = threadIdx.x, lane = tid & 31, warp = tid >> 5;
    const int qr = lane >> 2, ql = lane & 3;
    const size_t rowbase = (size_t)b * LSEQ + seg * SEGLEN;
    const size_t hpb = ((size_t)bh * NSEG + seg) * STATEPAIRS;

    const int lrow = lane & 15;
    const int lkp  = (lane >> 4) << 2;
    const int brow = ((lane >> 4) << 3) + (lane & 7);
    const int bkp  = ((lane >> 3) & 1) << 2;

    #pragma unroll
    for (int i = 0; i < 4; i++) {
        int e = tid + i * 256;
        int t = e >> 4, g = (e & 15) * 4;
        const size_t srcw = (rowbase + t) * 128 + 64 + g;
        CPA16((uint32_t)__cvta_generic_to_shared(&CH2[t*TSTRIDE + g]), g_bcH + srcw);
        CPA16((uint32_t)__cvta_generic_to_shared(&CL2[t*TSTRIDE + g]), g_bcL + srcw);
    }
    #pragma unroll
    for (int i = 0; i < 4; i++) {
        int e = tid + i * 256;
        int p = e >> 4, g = (e & 15) * 4;
        const size_t srcw = hpb + (size_t)p * 64 + g;
        CPA16((uint32_t)__cvta_generic_to_shared(&HHs[p*TSTRIDE + g]), g_hsH + srcw);
        CPA16((uint32_t)__cvta_generic_to_shared(&HLs[p*TSTRIDE + g]), g_hsL + srcw);
    }
    CPA_COMMIT();

    const float Aneg = -expf(A_log[h]);
    float vdt = 0.f, acs = 0.f;
    if (tid < SEGLEN) {
        vdt = g_dt[(rowbase + tid) * NHEADS + h];
        acs = vdt;
        #pragma unroll
        for (int o = 1; o < 32; o <<= 1) {
            float nv = __shfl_up_sync(0xffffffffu, acs, o);
            if (lane >= o) acs += nv;
        }
        if (lane == 31) wsum2[warp] = acs;
    }
    __syncthreads();
    if (tid < SEGLEN) {
        float pre = (warp == 1) ? wsum2[0] : 0.f;
        su[tid] = __expf(Aneg * (acs + pre));
    }
    CPA_WAIT0();
    __syncthreads();

    float yreg[4][4];
    #pragma unroll
    for (int j = 0; j < 4; j++)
        #pragma unroll
        for (int r = 0; r < 4; r++) yreg[j][r] = 0.f;

    const int m2 = (warp >> 1) * 16, n2 = (warp & 1) * 32;
    #pragma unroll
    for (int kb = 0; kb < 8; kb++) {
        const int kp0 = kb * 8;
        uint32_t aH[4], aL[4], bH[4][2], bL[4][2];
        {
            const int r = (m2 + lrow) * TSTRIDE + kp0 + lkp;
            uint32_t ad = (uint32_t)__cvta_generic_to_shared(&CH2[r]);
            LDSM_X4(aH[0], aH[1], aH[2], aH[3], ad);
            ad = (uint32_t)__cvta_generic_to_shared(&CL2[r]);
            LDSM_X4(aL[0], aL[1], aL[2], aL[3], ad);
        }
        #pragma unroll
        for (int nf2 = 0; nf2 < 2; nf2++) {
            const int r = (n2 + brow + nf2*16) * TSTRIDE + kp0 + bkp;
            uint32_t bd = (uint32_t)__cvta_generic_to_shared(&HHs[r]);
            LDSM_X4(bH[2*nf2][0], bH[2*nf2][1], bH[2*nf2+1][0], bH[2*nf2+1][1], bd);
            bd = (uint32_t)__cvta_generic_to_shared(&HLs[r]);
            LDSM_X4(bL[2*nf2][0], bL[2*nf2][1], bL[2*nf2+1][0], bL[2*nf2+1][1], bd);
        }
        #pragma unroll
        for (int nf = 0; nf < 4; nf++)
            MMA3B(yreg[nf], aH, aL, bH[nf], bL[nf]);
    }

    {
        int t = m2 + qr;
        float u0 = su[t], u1 = su[t + 8];
        #pragma unroll
        for (int nf = 0; nf < 4; nf++) {
            int p0 = n2 + nf*8 + ql*2;
            float* addr0 = &g_y[(rowbase + t)*DINNER + h*HEADDIM + p0];
            float* addr1 = &g_y[(rowbase + t + 8)*DINNER + h*HEADDIM + p0];
            float2 o0 = *(float2*)addr0;
            float2 o1 = *(float2*)addr1;
            o0.x += u0 * yreg[nf][0];  o0.y += u0 * yreg[nf][1];
            o1.x += u1 * yreg[nf][2];  o1.y += u1 * yreg[nf][3];
            *(float2*)addr0 = o0;
            *(float2*)addr1 = o1;
        }
    }
}

// =================================================================
// gate+norm: y = y*silu(z); rmsnorm; emit packed fp16 pairs
// =================================================================
__global__ __launch_bounds__(256) void gate_norm_kernel(const float* __restrict__ norm_w)
{
    const int row = blockIdx.x;
    const int tid = threadIdx.x;
    const float* zrow = g_zxbcdt + (size_t)row * DPROJ;
    const float* yrow = g_y + (size_t)row * DINNER;

    float2 v[3];
    float ss = 0.f;
    #pragma unroll
    for (int i = 0; i < 3; i++) {
        int p = tid + i*256;
        float2 z2 = *(const float2*)&zrow[2*p];
        float2 y2 = *(const float2*)&yrow[2*p];
        float g0 = y2.x * (z2.x / (1.f + expf(-z2.x)));
        float g1 = y2.y * (z2.y / (1.f + expf(-z2.y)));
        v[i] = make_float2(g0, g1);
        ss += g0*g0 + g1*g1;
    }
    #pragma unroll
    for (int o = 16; o > 0; o >>= 1) ss += __shfl_xor_sync(0xffffffffu, ss, o);
    __shared__ float red[8];
    if ((tid & 31) == 0) red[tid >> 5] = ss;
    __syncthreads();
    if (tid < 32) {
        float s2 = (tid < 8) ? red[tid] : 0.f;
        #pragma unroll
        for (int o = 4; o > 0; o >>= 1) s2 += __shfl_xor_sync(0xffffffffu, s2, o);
        if (tid == 0) red[0] = s2;
    }
    __syncthreads();
    const float rstd = rsqrtf(red[0] * (1.f/1536.f) + 1e-5f);
    #pragma unroll
    for (int i = 0; i < 3; i++) {
        int p = tid + i*256;
        float2 w2 = *(const float2*)&norm_w[2*p];
        g_y16[(size_t)row * (DINNER/2) + p] =
            packh2(v[i].x * rstd * w2.x, v[i].y * rstd * w2.y);
    }
}

// =================================================================
extern "C" void kernel_launch(void* const* d_in, const int* in_sizes, int n_in,
                              void* d_out, int out_size)
{
    const float* feature   = (const float*)d_in[0];
    const float* in_proj_w = (const float*)d_in[1];
    const float* conv_w    = (const float*)d_in[2];
    const float* conv_b    = (const float*)d_in[3];
    const float* dt_bias   = (const float*)d_in[4];
    const float* A_log     = (const float*)d_in[5];
    const float* Dvec      = (const float*)d_in[6];
    const float* norm_w    = (const float*)d_in[7];
    const float* out_projw = (const float*)d_in[8];
    const float* gate1     = (const float*)d_in[9];
    float* out = (float*)d_out;

    float *zx;
    uint32_t *f16, *iw16, *ow16, *y16;
    cudaGetSymbolAddress((void**)&zx,   g_zxbcdt);
    cudaGetSymbolAddress((void**)&f16,  g_feat16);
    cudaGetSymbolAddress((void**)&iw16, g_ipw16);
    cudaGetSymbolAddress((void**)&ow16, g_opw16);
    cudaGetSymbolAddress((void**)&y16,  g_y16);

    cudaFuncSetAttribute(gemm_fp16,
        cudaFuncAttributeMaxDynamicSharedMemorySize, GP_SMEM);
    cudaFuncSetAttribute(gemm_fp16_bm64,
        cudaFuncAttributeMaxDynamicSharedMemorySize, GQ_SMEM);
    cudaFuncSetAttribute(chunk_fused_kernel,
        cudaFuncAttributeMaxDynamicSharedMemorySize, K1_SMEM_U32 * 4);
    cudaFuncSetAttribute(inter_kernel,
        cudaFuncAttributeMaxDynamicSharedMemorySize, K3_SMEM_U32 * 4);

    dim3 blk(256);

    tofp16_kernel<<<(ROWS*DMODEL/2)/256, blk>>>(feature, f16);
    tofp16_kernel<<<(DPROJ*DMODEL/2)/256, blk>>>(in_proj_w, iw16);
    tofp16_kernel<<<(DMODEL*DINNER/2)/256, blk>>>(out_projw, ow16);

    gemm_fp16<<<dim3((DPROJ + 127)/128, ROWS/128), blk, GP_SMEM>>>(
        f16, iw16, zx, ROWS, DPROJ, DMODEL/2, nullptr);

    conv_silu_kernel<<<(int)(((long)ROWS * (CONVDIM/2)) / 256), blk>>>(conv_w, conv_b);
    dt_kernel<<<(ROWS * NHEADS) / 256, blk>>>(dt_bias);

    chunk_fused_kernel<<<BATCH * NHEADS * NSEG, blk, K1_SMEM_U32 * 4>>>(A_log, Dvec);
    combine_kernel<<<BATCH * NHEADS, blk>>>(A_log);
    inter_kernel<<<BATCH * NHEADS * NSEG, blk, K3_SMEM_U32 * 4>>>(A_log);

    gate_norm_kernel<<<ROWS, blk>>>(norm_w);

    // out_proj: BM=64 variant — grid 6 x 128 = 768 CTAs, 3 CTAs/SM
    gemm_fp16_bm64<<<dim3(DMODEL/128, ROWS/64), blk, GQ_SMEM>>>(
        y16, ow16, out, ROWS, DMODEL, DINNER/2, gate1);
}

// round 17
// speedup vs baseline: 1.0056x; 1.0056x over previous
#include <cuda_runtime.h>
#include <cuda_fp16.h>
#include <math.h>
#include <stdint.h>

#define BATCH   4
#define LSEQ    2048
#define ROWS    (BATCH*LSEQ)      // 8192
#define DMODEL  768
#define DINNER  1536
#define NHEADS  24
#define HEADDIM 64
#define DSTATE  128
#define CONVDIM 1792
#define DPROJ   3352

#define NSEG    32
#define SEGLEN  (LSEQ/NSEG)       // 64
#define STATESZ (HEADDIM*DSTATE)  // 8192
#define STATEPAIRS (STATESZ/2)    // 4096

// -------- scratch (device globals; no allocation allowed) --------
__device__ float g_zxbcdt[(size_t)ROWS * DPROJ];
__device__ float g_xBC[(size_t)ROWS * CONVDIM];
__device__ float g_dt[ROWS * NHEADS];
__device__ float g_y[(size_t)ROWS * DINNER];
__device__ float g_states[(size_t)BATCH*NHEADS*NSEG*STATESZ];
// pre-split bf16 hi/lo of xBC's B|C columns: [row][128 pairs]
__device__ uint32_t g_bcH[(size_t)ROWS*128];
__device__ uint32_t g_bcL[(size_t)ROWS*128];
// pre-split bf16 hi/lo segment start states
__device__ uint32_t g_hsH[(size_t)BATCH*NHEADS*NSEG*STATEPAIRS];
__device__ uint32_t g_hsL[(size_t)BATCH*NHEADS*NSEG*STATEPAIRS];
// fp16 packed-pair operands for projection GEMMs
__device__ uint32_t g_feat16[(size_t)ROWS*DMODEL/2];
__device__ uint32_t g_ipw16[(size_t)DPROJ*DMODEL/2];
__device__ uint32_t g_opw16[(size_t)DMODEL*DINNER/2];
__device__ uint32_t g_y16[(size_t)ROWS*DINNER/2];

// conversion sizes (float pairs)
#define NCV1 (ROWS*DMODEL/2)              // feature
#define NCV2 (DPROJ*DMODEL/2)             // in_proj_w
#define NCV3 (DMODEL*DINNER/2)            // out_proj_w
#define NCVT (NCV1 + NCV2 + NCV3)         // 5022720 (= 19620 * 256)

// =================================================================
// helpers
// =================================================================
__device__ __forceinline__ uint32_t packbf2(float f0, float f1) {
    uint32_t r;
    asm("cvt.rn.bf16x2.f32 %0, %1, %2;" : "=r"(r) : "f"(f1), "f"(f0));
    return r;
}
__device__ __forceinline__ void bsplit2(float f0, float f1, uint32_t& H, uint32_t& L) {
    H = packbf2(f0, f1);
    float h0 = __uint_as_float(H << 16);
    float h1 = __uint_as_float(H & 0xffff0000u);
    L = packbf2(f0 - h0, f1 - h1);
}
__device__ __forceinline__ uint32_t packh2(float f0, float f1) {
    __half2 h = __float22half2_rn(make_float2(f0, f1));
    return *(uint32_t*)&h;
}
__device__ __forceinline__ float ubf(uint32_t w, int hi) {
    return __uint_as_float(hi ? (w & 0xffff0000u) : (w << 16));
}

#define CPA16(dst, src) \
    asm volatile("cp.async.cg.shared.global [%0], [%1], 16;\n" \
                 :: "r"(dst), "l"(src))
#define CPA16P(dst, src, valid) \
    asm volatile("cp.async.cg.shared.global [%0], [%1], 16, %2;\n" \
                 :: "r"(dst), "l"(src), "r"((valid) ? 16 : 0))
#define CPA_COMMIT() asm volatile("cp.async.commit_group;\n" ::: "memory")
#define CPA_WAIT0()  asm volatile("cp.async.wait_group 0;\n" ::: "memory")
#define CPA_WAIT1()  asm volatile("cp.async.wait_group 1;\n" ::: "memory")

#define MMA_BF16(d, a, b) \
    asm volatile("mma.sync.aligned.m16n8k16.row.col.f32.bf16.bf16.f32 " \
                 "{%0,%1,%2,%3},{%4,%5,%6,%7},{%8,%9},{%0,%1,%2,%3};\n" \
                 : "+f"((d)[0]), "+f"((d)[1]), "+f"((d)[2]), "+f"((d)[3]) \
                 : "r"((a)[0]), "r"((a)[1]), "r"((a)[2]), "r"((a)[3]), \
                   "r"((b)[0]), "r"((b)[1]))
#define MMA_F16(d, a, b) \
    asm volatile("mma.sync.aligned.m16n8k16.row.col.f32.f16.f16.f32 " \
                 "{%0,%1,%2,%3},{%4,%5,%6,%7},{%8,%9},{%0,%1,%2,%3};\n" \
                 : "+f"((d)[0]), "+f"((d)[1]), "+f"((d)[2]), "+f"((d)[3]) \
                 : "r"((a)[0]), "r"((a)[1]), "r"((a)[2]), "r"((a)[3]), \
                   "r"((b)[0]), "r"((b)[1]))
#define MMA3B(d, aH, aL, bH, bL) do { \
    MMA_BF16(d, aL, bH); \
    MMA_BF16(d, aH, bL); \
    MMA_BF16(d, aH, bH); } while (0)

#define LDSM_X4(r0, r1, r2, r3, a) \
    asm volatile("ldmatrix.sync.aligned.m8n8.x4.shared.b16 {%0,%1,%2,%3}, [%4];" \
                 : "=r"(r0), "=r"(r1), "=r"(r2), "=r"(r3) : "r"(a))

#define TSTRIDE 68   // words per 64-pair tile row (C/B initial, inter tiles)
#define XSTRIDE 36   // words per 32-pair tile row (X, M~ k, wB)

// =================================================================
// fused fp32 -> packed fp16 conversion (feature | in_proj_w | out_proj_w)
// =================================================================
__global__ __launch_bounds__(256) void tofp16_all_kernel(
    const float* __restrict__ feat, const float* __restrict__ ipw,
    const float* __restrict__ opw)
{
    const int idx = blockIdx.x * 256 + threadIdx.x;
    const float* s;
    uint32_t* d;
    int j;
    if (idx < NCV1)            { s = feat; d = g_feat16; j = idx; }
    else if (idx < NCV1+NCV2)  { s = ipw;  d = g_ipw16;  j = idx - NCV1; }
    else                       { s = opw;  d = g_opw16;  j = idx - NCV1 - NCV2; }
    float2 v = ((const float2*)s)[j];
    d[j] = packh2(v.x, v.y);
}

// =================================================================
// fp16 tensor-core GEMM (NT): BM=128, 3-stage cp.async (R14 passing)
// =================================================================
#define GP_STAGE 5120
#define GP_SMEM  (3 * GP_STAGE * 4)

__global__ __launch_bounds__(256) void gemm_fp16(
    const uint32_t* __restrict__ A16, const uint32_t* __restrict__ B16,
    float* __restrict__ C, int M, int N, int Kp,
    const float* __restrict__ gate)
{
    extern __shared__ uint32_t gsm[];

    const int tid  = threadIdx.x;
    const int lane = tid & 31;
    const int warp = tid >> 5;
    const int wm   = warp >> 2;
    const int wn   = warp & 3;
    const int m0   = blockIdx.y * 128;
    const int n0   = blockIdx.x * 128;
    const int qr   = lane >> 2;
    const int ql   = lane & 3;

    const uint32_t* csrc[4];
    int coff[4];
    bool cval[4];
    #pragma unroll
    for (int q = 0; q < 4; q++) {
        int e = tid + q * 256;
        bool isB = e >= 512;
        int r = (e & 511) >> 2;
        int g = (e & 3) * 4;
        coff[q] = (isB ? 2560 : 0) + r * 20 + g;
        int grow = isB ? min(n0 + r, N - 1) : (m0 + r);
        cval[q] = isB ? ((n0 + r) < N) : true;
        csrc[q] = (isB ? B16 : A16) + (size_t)grow * Kp + g;
    }

    const int a_row = wm * 64 + (lane & 15);
    const int a_kp  = (lane >> 4) << 2;
    const int b_row = wn * 32 + ((lane >> 4) << 3) + (lane & 7);
    const int b_kp  = ((lane >> 3) & 1) << 2;

    float acc[4][4][4];
    #pragma unroll
    for (int i = 0; i < 4; i++)
        #pragma unroll
        for (int j = 0; j < 4; j++)
            #pragma unroll
            for (int r = 0; r < 4; r++) acc[i][j][r] = 0.f;

    const int KT = Kp / 16;

    #define GF_FILL(kt, s)                                                       \
    {                                                                            \
        const size_t ko = (size_t)(kt) * 16;                                     \
        uint32_t* stg = gsm + (s) * GP_STAGE;                                    \
        _Pragma("unroll")                                                        \
        for (int q = 0; q < 4; q++) {                                            \
            uint32_t d = (uint32_t)__cvta_generic_to_shared(&stg[coff[q]]);      \
            CPA16P(d, csrc[q] + ko, cval[q]);                                    \
        }                                                                        \
        CPA_COMMIT();                                                            \
    }

    GF_FILL(0, 0);
    if (KT > 1) GF_FILL(1, 1);

    int st = 0;
    for (int kt = 0; kt < KT; kt++) {
        if (kt + 1 < KT) { CPA_WAIT1(); } else { CPA_WAIT0(); }
        __syncthreads();

        if (kt + 2 < KT) {
            int ns = st + 2; if (ns >= 3) ns -= 3;
            GF_FILL(kt + 2, ns);
        }

        const uint32_t* As_ = gsm + st * GP_STAGE;
        const uint32_t* Bs_ = As_ + 2560;

        #pragma unroll
        for (int kb = 0; kb < 2; kb++) {
            const int kp0 = kb * 8;
            uint32_t a[4][4], b[4][2];
            #pragma unroll
            for (int mf = 0; mf < 4; mf++) {
                uint32_t ad = (uint32_t)__cvta_generic_to_shared(
                    &As_[(a_row + mf * 16) * 20 + kp0 + a_kp]);
                LDSM_X4(a[mf][0], a[mf][1], a[mf][2], a[mf][3], ad);
            }
            #pragma unroll
            for (int nf2 = 0; nf2 < 2; nf2++) {
                uint32_t bd = (uint32_t)__cvta_generic_to_shared(
                    &Bs_[(b_row + nf2 * 16) * 20 + kp0 + b_kp]);
                LDSM_X4(b[2*nf2][0], b[2*nf2][1], b[2*nf2+1][0], b[2*nf2+1][1], bd);
            }
            #pragma unroll
            for (int mf = 0; mf < 4; mf++)
                #pragma unroll
                for (int nf = 0; nf < 4; nf++)
                    MMA_F16(acc[mf][nf], a[mf], b[nf]);
        }

        st++; if (st >= 3) st = 0;
    }
    #undef GF_FILL

    float scale = 1.f;
    if (gate) { float g = *gate; scale = 1.f / (1.f + expf(-g)); }

    #pragma unroll
    for (int mf = 0; mf < 4; mf++) {
        const int r = m0 + wm * 64 + mf * 16 + qr;
        #pragma unroll
        for (int nf = 0; nf < 4; nf++) {
            const int c = n0 + wn * 32 + nf * 8 + ql * 2;
            if (c < N) {
                float2 v0 = make_float2(acc[mf][nf][0] * scale, acc[mf][nf][1] * scale);
                float2 v1 = make_float2(acc[mf][nf][2] * scale, acc[mf][nf][3] * scale);
                *(float2*)&C[(size_t)r * N + c]       = v0;
                *(float2*)&C[(size_t)(r + 8) * N + c] = v1;
            }
        }
    }
}

// =================================================================
// conv_silu (pairwise) + fused bf16 split of B|C + fused dt softplus
// per-row units: u<896 conv pair; u in [896,908) -> dt heads 2(u-896),+1
// =================================================================
#define ROWUNITS 908

__global__ __launch_bounds__(256) void conv_silu_kernel(
    const float* __restrict__ conv_w, const float* __restrict__ conv_b,
    const float* __restrict__ dt_bias)
{
    const long idx = (long)blockIdx.x * 256 + threadIdx.x;   // < ROWS*908
    const int  u   = (int)(idx % ROWUNITS);
    const long row = idx / ROWUNITS;
    const int  l   = (int)(row % LSEQ);

    if (u >= CONVDIM/2) {
        // dt: heads 2d, 2d+1
        const int d = u - CONVDIM/2;          // 0..11
        const int h0 = 2*d;
        const float* src = g_zxbcdt + (size_t)row * DPROJ + (DINNER + CONVDIM) + h0;
        float2 v = make_float2(src[0] + dt_bias[h0], src[1] + dt_bias[h0+1]);
        float sp0 = (v.x > 20.f) ? v.x : log1pf(expf(v.x));
        float sp1 = (v.y > 20.f) ? v.y : log1pf(expf(v.y));
        g_dt[row * NHEADS + h0]     = sp0;
        g_dt[row * NHEADS + h0 + 1] = sp1;
        return;
    }

    const int c = u * 2;
    float2 acc = make_float2(conv_b[c], conv_b[c+1]);
    float4 wa = *(const float4*)&conv_w[c*4];
    float4 wb = *(const float4*)&conv_w[(c+1)*4];
    const float* base = g_zxbcdt + (size_t)row * DPROJ + DINNER + c;
    if (l >= 3) { float2 v = *(const float2*)(base - 3*DPROJ);
                  acc.x = fmaf(v.x, wa.x, acc.x); acc.y = fmaf(v.y, wb.x, acc.y); }
    if (l >= 2) { float2 v = *(const float2*)(base - 2*DPROJ);
                  acc.x = fmaf(v.x, wa.y, acc.x); acc.y = fmaf(v.y, wb.y, acc.y); }
    if (l >= 1) { float2 v = *(const float2*)(base - 1*DPROJ);
                  acc.x = fmaf(v.x, wa.z, acc.x); acc.y = fmaf(v.y, wb.z, acc.y); }
    { float2 v = *(const float2*)base;
      acc.x = fmaf(v.x, wa.w, acc.x); acc.y = fmaf(v.y, wb.w, acc.y); }

    acc.x = acc.x / (1.f + expf(-acc.x));
    acc.y = acc.y / (1.f + expf(-acc.y));
    *(float2*)&g_xBC[row * CONVDIM + c] = acc;

    if (c >= DINNER) {
        const int np = (c - DINNER) >> 1;
        uint32_t hh, ll;
        bsplit2(acc.x, acc.y, hh, ll);
        g_bcH[row * 128 + np] = hh;
        g_bcL[row * 128 + np] = ll;
    }
}

// =================================================================
// K1: fused per-chunk kernel — T=64, 256 threads (R15 passing)
// =================================================================
#define K1_SMEM_U32 22724
#define K3_SMEM_U32 17476

__global__ __launch_bounds__(256) void chunk_fused_kernel(
    const float* __restrict__ A_log, const float* __restrict__ Dvec)
{
    extern __shared__ uint32_t smu[];
    uint32_t* CHs = smu;
    uint32_t* CLs = smu + 4352;
    uint32_t* BHs = smu + 8704;
    uint32_t* BLs = smu + 13312;
    uint32_t* XHs = smu + 17920;
    uint32_t* XLs = smu + 20224;
    float*    sa  = (float*)(smu + 22528);
    float*    sdt = (float*)(smu + 22592);
    float*    sw  = (float*)(smu + 22656);
    float*    wsum2 = (float*)(smu + 22720);

    const int blk = blockIdx.x;
    const int bh = blk >> 5, seg = blk & (NSEG - 1);
    const int b = bh / NHEADS, h = bh % NHEADS;
    const int tid = threadIdx.x, lane = tid & 31, warp = tid >> 5;
    const int qr = lane >> 2, ql = lane & 3;
    const size_t rowbase = (size_t)b * LSEQ + seg * SEGLEN;

    const int lrow = lane & 15;
    const int lkp  = (lane >> 4) << 2;
    const int brow = ((lane >> 4) << 3) + (lane & 7);
    const int bkp  = ((lane >> 3) & 1) << 2;

    #pragma unroll
    for (int i = 0; i < 4; i++) {
        int e = tid + i * 256;
        int t = e >> 4, g = (e & 15) * 4;
        const size_t srcw = (rowbase + t) * 128 + g;
        CPA16((uint32_t)__cvta_generic_to_shared(&BHs[t*TSTRIDE + g]), g_bcH + srcw);
        CPA16((uint32_t)__cvta_generic_to_shared(&BLs[t*TSTRIDE + g]), g_bcL + srcw);
        CPA16((uint32_t)__cvta_generic_to_shared(&CHs[t*TSTRIDE + g]), g_bcH + srcw + 64);
        CPA16((uint32_t)__cvta_generic_to_shared(&CLs[t*TSTRIDE + g]), g_bcL + srcw + 64);
    }
    CPA_COMMIT();

    #pragma unroll
    for (int i = 0; i < 8; i++) {
        int e = tid + i * 256;
        int p = e & 63, sp = e >> 6;
        const float* s0 = g_xBC + (rowbase + 2*sp) * CONVDIM + h * HEADDIM + p;
        uint32_t hh, ll;
        bsplit2(s0[0], s0[CONVDIM], hh, ll);
        XHs[p*XSTRIDE + sp] = hh; XLs[p*XSTRIDE + sp] = ll;
    }

    const float Aneg = -expf(A_log[h]);
    float vdt = 0.f, acs = 0.f;
    if (tid < SEGLEN) {
        vdt = g_dt[(rowbase + tid) * NHEADS + h];
        acs = vdt;
        #pragma unroll
        for (int o = 1; o < 32; o <<= 1) {
            float nv = __shfl_up_sync(0xffffffffu, acs, o);
            if (lane >= o) acs += nv;
        }
        if (lane == 31) wsum2[warp] = acs;
    }
    __syncthreads();
    if (tid < SEGLEN) {
        float tot = wsum2[0] + wsum2[1];
        float pre = (warp == 1) ? wsum2[0] : 0.f;
        float a = acs + pre;
        sa[tid]  = a;
        sdt[tid] = vdt;
        sw[tid]  = vdt * __expf(Aneg * (tot - a));
    }
    CPA_WAIT0();
    __syncthreads();

    // GEMM1: M = C @ B^T (64x64, K=128), skip masked warp tiles
    float mreg[4][4];
    #pragma unroll
    for (int j = 0; j < 4; j++)
        #pragma unroll
        for (int r = 0; r < 4; r++) mreg[j][r] = 0.f;

    const int m1 = (warp >> 1) * 16, n1 = (warp & 1) * 32;
    if (n1 < m1 + 16) {
        #pragma unroll
        for (int kb = 0; kb < 8; kb++) {
            const int kp0 = kb * 8;
            uint32_t aH[4], aL[4], bH[4][2], bL[4][2];
            {
                const int r = (m1 + lrow) * TSTRIDE + kp0 + lkp;
                uint32_t ad = (uint32_t)__cvta_generic_to_shared(&CHs[r]);
                LDSM_X4(aH[0], aH[1], aH[2], aH[3], ad);
                ad = (uint32_t)__cvta_generic_to_shared(&CLs[r]);
                LDSM_X4(aL[0], aL[1], aL[2], aL[3], ad);
            }
            #pragma unroll
            for (int nf2 = 0; nf2 < 2; nf2++) {
                const int r = (n1 + brow + nf2*16) * TSTRIDE + kp0 + bkp;
                uint32_t bd = (uint32_t)__cvta_generic_to_shared(&BHs[r]);
                LDSM_X4(bH[2*nf2][0], bH[2*nf2][1], bH[2*nf2+1][0], bH[2*nf2+1][1], bd);
                bd = (uint32_t)__cvta_generic_to_shared(&BLs[r]);
                LDSM_X4(bL[2*nf2][0], bL[2*nf2][1], bL[2*nf2+1][0], bL[2*nf2+1][1], bd);
            }
            #pragma unroll
            for (int nf = 0; nf < 4; nf++)
                MMA3B(mreg[nf], aH, aL, bH[nf], bL[nf]);
        }
    }
    __syncthreads();

    {
        int tA = m1 + qr, tB = tA + 8;
        float aA = sa[tA], aB = sa[tB];
        #pragma unroll
        for (int nf = 0; nf < 4; nf++) {
            int sp = (n1 >> 1) + nf*4 + ql;
            int s0 = 2*sp, s1 = s0 + 1;
            float as0 = sa[s0], as1 = sa[s1];
            float d0 = sdt[s0], d1 = sdt[s1];
            float v00 = (s0 <= tA) ? mreg[nf][0] * __expf(Aneg*(aA-as0)) * d0 : 0.f;
            float v01 = (s1 <= tA) ? mreg[nf][1] * __expf(Aneg*(aA-as1)) * d1 : 0.f;
            float v10 = (s0 <= tB) ? mreg[nf][2] * __expf(Aneg*(aB-as0)) * d0 : 0.f;
            float v11 = (s1 <= tB) ? mreg[nf][3] * __expf(Aneg*(aB-as1)) * d1 : 0.f;
            uint32_t hh, ll;
            bsplit2(v00, v01, hh, ll); CHs[tA*TSTRIDE + sp] = hh; CLs[tA*TSTRIDE + sp] = ll;
            bsplit2(v10, v11, hh, ll); CHs[tB*TSTRIDE + sp] = hh; CLs[tB*TSTRIDE + sp] = ll;
        }
    }

    #pragma unroll
    for (int i = 0; i < 16; i++) {
        int e = tid + i * 256;
        int n = e & 127, sp = e >> 7;
        const float* s0 = g_xBC + (rowbase + 2*sp) * CONVDIM + DINNER + n;
        float f0 = s0[0] * sw[2*sp];
        float f1 = s0[CONVDIM] * sw[2*sp + 1];
        uint32_t hh, ll;
        bsplit2(f0, f1, hh, ll);
        BHs[n*XSTRIDE + sp] = hh; BLs[n*XSTRIDE + sp] = ll;
    }
    __syncthreads();

    // GEMM2: Y = M~ @ X (64t x 64p, K=64)
    {
        float yreg[4][4];
        #pragma unroll
        for (int j = 0; j < 4; j++)
            #pragma unroll
            for (int r = 0; r < 4; r++) yreg[j][r] = 0.f;

        const int m2 = (warp >> 1) * 16, n2 = (warp & 1) * 32;
        #pragma unroll
        for (int kb = 0; kb < 4; kb++) {
            const int kp0 = kb * 8;
            uint32_t aH[4], aL[4], bH[4][2], bL[4][2];
            {
                const int r = (m2 + lrow) * TSTRIDE + kp0 + lkp;
                uint32_t ad = (uint32_t)__cvta_generic_to_shared(&CHs[r]);
                LDSM_X4(aH[0], aH[1], aH[2], aH[3], ad);
                ad = (uint32_t)__cvta_generic_to_shared(&CLs[r]);
                LDSM_X4(aL[0], aL[1], aL[2], aL[3], ad);
            }
            #pragma unroll
            for (int nf2 = 0; nf2 < 2; nf2++) {
                const int r = (n2 + brow + nf2*16) * XSTRIDE + kp0 + bkp;
                uint32_t bd = (uint32_t)__cvta_generic_to_shared(&XHs[r]);
                LDSM_X4(bH[2*nf2][0], bH[2*nf2][1], bH[2*nf2+1][0], bH[2*nf2+1][1], bd);
                bd = (uint32_t)__cvta_generic_to_shared(&XLs[r]);
                LDSM_X4(bL[2*nf2][0], bL[2*nf2][1], bL[2*nf2+1][0], bL[2*nf2+1][1], bd);
            }
            #pragma unroll
            for (int nf = 0; nf < 4; nf++)
                MMA3B(yreg[nf], aH, aL, bH[nf], bL[nf]);
        }

        const float Dh = Dvec[h];
        {
            int t = m2 + qr;
            const int sp0 = t >> 1, hi0 = t & 1;
            const int sp1 = (t + 8) >> 1, hi1 = t & 1;
            #pragma unroll
            for (int nf = 0; nf < 4; nf++) {
                int p0 = n2 + nf*8 + ql*2;
                float x00 = ubf(XHs[p0*XSTRIDE + sp0], hi0) + ubf(XLs[p0*XSTRIDE + sp0], hi0);
                float x01 = ubf(XHs[(p0+1)*XSTRIDE + sp0], hi0) + ubf(XLs[(p0+1)*XSTRIDE + sp0], hi0);
                float x10 = ubf(XHs[p0*XSTRIDE + sp1], hi1) + ubf(XLs[p0*XSTRIDE + sp1], hi1);
                float x11 = ubf(XHs[(p0+1)*XSTRIDE + sp1], hi1) + ubf(XLs[(p0+1)*XSTRIDE + sp1], hi1);
                float2 o;
                o.x = yreg[nf][0] + Dh * x00;
                o.y = yreg[nf][1] + Dh * x01;
                *(float2*)&g_y[(rowbase + t)*DINNER + h*HEADDIM + p0] = o;
                o.x = yreg[nf][2] + Dh * x10;
                o.y = yreg[nf][3] + Dh * x11;
                *(float2*)&g_y[(rowbase + t + 8)*DINNER + h*HEADDIM + p0] = o;
            }
        }
    }

    // GEMM3: S = X^T @ (w*B) (64p x 128n, K=64)
    {
        float sreg[2][4][4];
        #pragma unroll
        for (int i = 0; i < 2; i++)
            #pragma unroll
            for (int j = 0; j < 4; j++)
                #pragma unroll
                for (int r = 0; r < 4; r++) sreg[i][j][r] = 0.f;

        const int m3 = (warp >> 2) * 32, n3 = (warp & 3) * 32;
        #pragma unroll
        for (int kb = 0; kb < 4; kb++) {
            const int kp0 = kb * 8;
            uint32_t aH[2][4], aL[2][4], bH[4][2], bL[4][2];
            #pragma unroll
            for (int mf = 0; mf < 2; mf++) {
                const int r = (m3 + lrow + mf*16) * XSTRIDE + kp0 + lkp;
                uint32_t ad = (uint32_t)__cvta_generic_to_shared(&XHs[r]);
                LDSM_X4(aH[mf][0], aH[mf][1], aH[mf][2], aH[mf][3], ad);
                ad = (uint32_t)__cvta_generic_to_shared(&XLs[r]);
                LDSM_X4(aL[mf][0], aL[mf][1], aL[mf][2], aL[mf][3], ad);
            }
            #pragma unroll
            for (int nf2 = 0; nf2 < 2; nf2++) {
                const int r = (n3 + brow + nf2*16) * XSTRIDE + kp0 + bkp;
                uint32_t bd = (uint32_t)__cvta_generic_to_shared(&BHs[r]);
                LDSM_X4(bH[2*nf2][0], bH[2*nf2][1], bH[2*nf2+1][0], bH[2*nf2+1][1], bd);
                bd = (uint32_t)__cvta_generic_to_shared(&BLs[r]);
                LDSM_X4(bL[2*nf2][0], bL[2*nf2][1], bL[2*nf2+1][0], bL[2*nf2+1][1], bd);
            }
            #pragma unroll
            for (int mf = 0; mf < 2; mf++)
                #pragma unroll
                for (int nf = 0; nf < 4; nf++)
                    MMA3B(sreg[mf][nf], aH[mf], aL[mf], bH[nf], bL[nf]);
        }

        const size_t sbase = ((size_t)bh * NSEG + seg) * STATESZ;
        #pragma unroll
        for (int mf = 0; mf < 2; mf++) {
            int p = m3 + mf*16 + qr;
            #pragma unroll
            for (int nf = 0; nf < 4; nf++) {
                int n0 = n3 + nf*8 + ql*2;
                float2 o0 = make_float2(sreg[mf][nf][0], sreg[mf][nf][1]);
                float2 o1 = make_float2(sreg[mf][nf][2], sreg[mf][nf][3]);
                *(float2*)&g_states[sbase + (size_t)p * DSTATE + n0]       = o0;
                *(float2*)&g_states[sbase + (size_t)(p + 8) * DSTATE + n0] = o1;
            }
        }
    }
}

// =================================================================
// K2: combine — NSEG=32, emits pre-split bf16 hi/lo hstart pairs
// =================================================================
__global__ __launch_bounds__(256) void combine_kernel(const float* __restrict__ A_log)
{
    const int bh = blockIdx.x;
    const int b = bh / NHEADS, h = bh % NHEADS;
    const int tid = threadIdx.x;

    __shared__ float part[256];
    __shared__ float Esh[NSEG];

    {
        const int k = tid >> 3, i = tid & 7;
        float s = 0.f;
        const size_t base = ((size_t)b*LSEQ + k*SEGLEN + i*8)*NHEADS + h;
        #pragma unroll
        for (int t = 0; t < 8; t++) s += g_dt[base + (size_t)t*NHEADS];
        part[tid] = s;
    }
    __syncthreads();
    if (tid < NSEG) {
        float s = 0.f;
        #pragma unroll
        for (int i = 0; i < 8; i++) s += part[tid*8 + i];
        Esh[tid] = expf(-expf(A_log[h]) * s);
    }
    __syncthreads();

    float2 hs[16];
    #pragma unroll
    for (int k2 = 0; k2 < 16; k2++) hs[k2] = make_float2(0.f, 0.f);

    for (int seg = 0; seg < NSEG; seg++) {
        const size_t pbase = ((size_t)bh*NSEG + seg)*STATEPAIRS;
        const float E = Esh[seg];
        #pragma unroll
        for (int k2 = 0; k2 < 16; k2++) {
            const size_t j = pbase + k2*256 + tid;
            uint32_t hh, ll;
            bsplit2(hs[k2].x, hs[k2].y, hh, ll);
            g_hsH[j] = hh;  g_hsL[j] = ll;
            float2 s = ((const float2*)g_states)[j];
            hs[k2].x = fmaf(hs[k2].x, E, s.x);
            hs[k2].y = fmaf(hs[k2].y, E, s.y);
        }
    }
}

// =================================================================
// K3: inter-chunk — T=64, 256 threads (R15 passing)
// =================================================================
__global__ __launch_bounds__(256) void inter_kernel(const float* __restrict__ A_log)
{
    extern __shared__ uint32_t smu[];
    uint32_t* CH2 = smu;
    uint32_t* CL2 = smu + 4352;
    uint32_t* HHs = smu + 8704;
    uint32_t* HLs = smu + 13056;
    float*    su  = (float*)(smu + 17408);
    float*    wsum2 = (float*)(smu + 17472);

    const int blk = blockIdx.x;
    const int bh = blk >> 5, seg = blk & (NSEG - 1);
    const int b = bh / NHEADS, h = bh % NHEADS;
    const int tid = threadIdx.x, lane = tid & 31, warp = tid >> 5;
    const int qr = lane >> 2, ql = lane & 3;
    const size_t rowbase = (size_t)b * LSEQ + seg * SEGLEN;
    const size_t hpb = ((size_t)bh * NSEG + seg) * STATEPAIRS;

    const int lrow = lane & 15;
    const int lkp  = (lane >> 4) << 2;
    const int brow = ((lane >> 4) << 3) + (lane & 7);
    const int bkp  = ((lane >> 3) & 1) << 2;

    #pragma unroll
    for (int i = 0; i < 4; i++) {
        int e = tid + i * 256;
        int t = e >> 4, g = (e & 15) * 4;
        const size_t srcw = (rowbase + t) * 128 + 64 + g;
        CPA16((uint32_t)__cvta_generic_to_shared(&CH2[t*TSTRIDE + g]), g_bcH + srcw);
        CPA16((uint32_t)__cvta_generic_to_shared(&CL2[t*TSTRIDE + g]), g_bcL + srcw);
    }
    #pragma unroll
    for (int i = 0; i < 4; i++) {
        int e = tid + i * 256;
        int p = e >> 4, g = (e & 15) * 4;
        const size_t srcw = hpb + (size_t)p * 64 + g;
        CPA16((uint32_t)__cvta_generic_to_shared(&HHs[p*TSTRIDE + g]), g_hsH + srcw);
        CPA16((uint32_t)__cvta_generic_to_shared(&HLs[p*TSTRIDE + g]), g_hsL + srcw);
    }
    CPA_COMMIT();

    const float Aneg = -expf(A_log[h]);
    float vdt = 0.f, acs = 0.f;
    if (tid < SEGLEN) {
        vdt = g_dt[(rowbase + tid) * NHEADS + h];
        acs = vdt;
        #pragma unroll
        for (int o = 1; o < 32; o <<= 1) {
            float nv = __shfl_up_sync(0xffffffffu, acs, o);
            if (lane >= o) acs += nv;
        }
        if (lane == 31) wsum2[warp] = acs;
    }
    __syncthreads();
    if (tid < SEGLEN) {
        float pre = (warp == 1) ? wsum2[0] : 0.f;
        su[tid] = __expf(Aneg * (acs + pre));
    }
    CPA_WAIT0();
    __syncthreads();

    float yreg[4][4];
    #pragma unroll
    for (int j = 0; j < 4; j++)
        #pragma unroll
        for (int r = 0; r < 4; r++) yreg[j][r] = 0.f;

    const int m2 = (warp >> 1) * 16, n2 = (warp & 1) * 32;
    #pragma unroll
    for (int kb = 0; kb < 8; kb++) {
        const int kp0 = kb * 8;
        uint32_t aH[4], aL[4], bH[4][2], bL[4][2];
        {
            const int r = (m2 + lrow) * TSTRIDE + kp0 + lkp;
            uint32_t ad = (uint32_t)__cvta_generic_to_shared(&CH2[r]);
            LDSM_X4(aH[0], aH[1], aH[2], aH[3], ad);
            ad = (uint32_t)__cvta_generic_to_shared(&CL2[r]);
            LDSM_X4(aL[0], aL[1], aL[2], aL[3], ad);
        }
        #pragma unroll
        for (int nf2 = 0; nf2 < 2; nf2++) {
            const int r = (n2 + brow + nf2*16) * TSTRIDE + kp0 + bkp;
            uint32_t bd = (uint32_t)__cvta_generic_to_shared(&HHs[r]);
            LDSM_X4(bH[2*nf2][0], bH[2*nf2][1], bH[2*nf2+1][0], bH[2*nf2+1][1], bd);
            bd = (uint32_t)__cvta_generic_to_shared(&HLs[r]);
            LDSM_X4(bL[2*nf2][0], bL[2*nf2][1], bL[2*nf2+1][0], bL[2*nf2+1][1], bd);
        }
        #pragma unroll
        for (int nf = 0; nf < 4; nf++)
            MMA3B(yreg[nf], aH, aL, bH[nf], bL[nf]);
    }

    {
        int t = m2 + qr;
        float u0 = su[t], u1 = su[t + 8];
        #pragma unroll
        for (int nf = 0; nf < 4; nf++) {
            int p0 = n2 + nf*8 + ql*2;
            float* addr0 = &g_y[(rowbase + t)*DINNER + h*HEADDIM + p0];
            float* addr1 = &g_y[(rowbase + t + 8)*DINNER + h*HEADDIM + p0];
            float2 o0 = *(float2*)addr0;
            float2 o1 = *(float2*)addr1;
            o0.x += u0 * yreg[nf][0];  o0.y += u0 * yreg[nf][1];
            o1.x += u1 * yreg[nf][2];  o1.y += u1 * yreg[nf][3];
            *(float2*)addr0 = o0;
            *(float2*)addr1 = o1;
        }
    }
}

// =================================================================
// gate+norm: y = y*silu(z); rmsnorm; emit packed fp16 pairs
// =================================================================
__global__ __launch_bounds__(256) void gate_norm_kernel(const float* __restrict__ norm_w)
{
    const int row = blockIdx.x;
    const int tid = threadIdx.x;
    const float* zrow = g_zxbcdt + (size_t)row * DPROJ;
    const float* yrow = g_y + (size_t)row * DINNER;

    float2 v[3];
    float ss = 0.f;
    #pragma unroll
    for (int i = 0; i < 3; i++) {
        int p = tid + i*256;
        float2 z2 = *(const float2*)&zrow[2*p];
        float2 y2 = *(const float2*)&yrow[2*p];
        float g0 = y2.x * (z2.x / (1.f + expf(-z2.x)));
        float g1 = y2.y * (z2.y / (1.f + expf(-z2.y)));
        v[i] = make_float2(g0, g1);
        ss += g0*g0 + g1*g1;
    }
    #pragma unroll
    for (int o = 16; o > 0; o >>= 1) ss += __shfl_xor_sync(0xffffffffu, ss, o);
    __shared__ float red[8];
    if ((tid & 31) == 0) red[tid >> 5] = ss;
    __syncthreads();
    if (tid < 32) {
        float s2 = (tid < 8) ? red[tid] : 0.f;
        #pragma unroll
        for (int o = 4; o > 0; o >>= 1) s2 += __shfl_xor_sync(0xffffffffu, s2, o);
        if (tid == 0) red[0] = s2;
    }
    __syncthreads();
    const float rstd = rsqrtf(red[0] * (1.f/1536.f) + 1e-5f);
    #pragma unroll
    for (int i = 0; i < 3; i++) {
        int p = tid + i*256;
        float2 w2 = *(const float2*)&norm_w[2*p];
        g_y16[(size_t)row * (DINNER/2) + p] =
            packh2(v[i].x * rstd * w2.x, v[i].y * rstd * w2.y);
    }
}

// =================================================================
extern "C" void kernel_launch(void* const* d_in, const int* in_sizes, int n_in,
                              void* d_out, int out_size)
{
    const float* feature   = (const float*)d_in[0];
    const float* in_proj_w = (const float*)d_in[1];
    const float* conv_w    = (const float*)d_in[2];
    const float* conv_b    = (const float*)d_in[3];
    const float* dt_bias   = (const float*)d_in[4];
    const float* A_log     = (const float*)d_in[5];
    const float* Dvec      = (const float*)d_in[6];
    const float* norm_w    = (const float*)d_in[7];
    const float* out_projw = (const float*)d_in[8];
    const float* gate1     = (const float*)d_in[9];
    float* out = (float*)d_out;

    float *zx;
    uint32_t *f16, *iw16, *ow16, *y16;
    cudaGetSymbolAddress((void**)&zx,   g_zxbcdt);
    cudaGetSymbolAddress((void**)&f16,  g_feat16);
    cudaGetSymbolAddress((void**)&iw16, g_ipw16);
    cudaGetSymbolAddress((void**)&ow16, g_opw16);
    cudaGetSymbolAddress((void**)&y16,  g_y16);

    cudaFuncSetAttribute(gemm_fp16,
        cudaFuncAttributeMaxDynamicSharedMemorySize, GP_SMEM);
    cudaFuncSetAttribute(chunk_fused_kernel,
        cudaFuncAttributeMaxDynamicSharedMemorySize, K1_SMEM_U32 * 4);
    cudaFuncSetAttribute(inter_kernel,
        cudaFuncAttributeMaxDynamicSharedMemorySize, K3_SMEM_U32 * 4);

    dim3 blk(256);

    // fused fp32->fp16 conversions (feature | in_proj_w | out_proj_w)
    tofp16_all_kernel<<<NCVT/256, blk>>>(feature, in_proj_w, out_projw);

    gemm_fp16<<<dim3((DPROJ + 127)/128, ROWS/128), blk, GP_SMEM>>>(
        f16, iw16, zx, ROWS, DPROJ, DMODEL/2, nullptr);

    // conv + silu + bc-split + dt softplus (fused)
    conv_silu_kernel<<<(int)(((long)ROWS * ROWUNITS) / 256), blk>>>(
        conv_w, conv_b, dt_bias);

    chunk_fused_kernel<<<BATCH * NHEADS * NSEG, blk, K1_SMEM_U32 * 4>>>(A_log, Dvec);
    combine_kernel<<<BATCH * NHEADS, blk>>>(A_log);
    inter_kernel<<<BATCH * NHEADS * NSEG, blk, K3_SMEM_U32 * 4>>>(A_log);

    gate_norm_kernel<<<ROWS, blk>>>(norm_w);

    gemm_fp16<<<dim3(DMODEL/128, ROWS/128), blk, GP_SMEM>>>(
        y16, ow16, out, ROWS, DMODEL, DINNER/2, gate1);
}